// round 15
// baseline (speedup 1.0000x reference)
#include <cuda_runtime.h>
#include <math.h>
#include <float.h>

#define MROWS   4096
#define NCOLS   16384
#define KHARD   163          // int(0.01 * (16384-1))
#define DELTA_W 5.0f
#define THR0    2.2f
#define NT      64           // 2 warps per CTA; each warp owns ONE row
#define NWARP   (NT / 32)
#define SLOTS   24           // per-lane private candidate slots
#define NB      256          // linear value bins over [THR0, THR0+4)
#define GCAP    64
#define GRIDSZ  2048         // 2048 CTAs x 2 warps = 4096 rows, single wave
#define SENT    0xFFFFFFFFu
#define FULLM   0xFFFFFFFFu

__device__ float    g_partials[MROWS];
__device__ unsigned g_done = 0;

__device__ __forceinline__ unsigned fkey(float x) {
    unsigned b = __float_as_uint(x);
    return (b & 0x80000000u) ? ~b : (b | 0x80000000u);
}
__device__ __forceinline__ float unfkey(unsigned k) {
    return (k & 0x80000000u) ? __uint_as_float(k ^ 0x80000000u) : __uint_as_float(~k);
}
__device__ __forceinline__ float softplus(float x) {
    return fmaxf(x, 0.0f) + __logf(1.0f + __expf(-fabsf(x)));
}
__device__ __forceinline__ int binof(float x) {          // x > THR0
    int b = (int)((x - THR0) * 64.0f);                   // NB/4 per unit
    return b > NB - 1 ? NB - 1 : b;
}

// Warp-level boundary-bin search for the r-th largest over hist[0..256).
// Writes wout = {bin, strictly-above count, bin count}; leaves wout[0]
// untouched (sentinel) if the histogram total is < r. Caller syncs the warp.
__device__ __forceinline__ void wselect256(const unsigned* __restrict__ hist,
                                           unsigned r, unsigned* wout)
{
    const int lane = threadIdx.x & 31;
    const int base = lane * 8;
    unsigned total = 0;
    #pragma unroll
    for (int j = 0; j < 8; ++j) total += hist[base + j];
    unsigned incl = total;                    // inclusive suffix over lanes
    #pragma unroll
    for (int off = 1; off < 32; off <<= 1) {
        unsigned v = __shfl_down_sync(FULLM, incl, off);
        if (lane + off < 32) incl += v;
    }
    unsigned above = incl - total;            // count in strictly-higher lanes
    if (above < r && incl >= r) {             // boundary in my 8 bins
        unsigned run = above;
        #pragma unroll
        for (int j = 7; j >= 0; --j) {
            unsigned cnt = hist[base + j];
            if (run + cnt >= r) { wout[0] = base + j; wout[1] = run; wout[2] = cnt; break; }
            run += cnt;
        }
    }
}

extern "C" __global__ void __launch_bounds__(NT)
mmcl_kernel(const float* __restrict__ in, const int* __restrict__ tg,
            float* __restrict__ out)
{
    __shared__ float    cand[NWARP][SLOTS * 32];   // per-warp private (6 KB)
    __shared__ unsigned hist[NWARP][NB];           // per-warp private (2 KB)
    __shared__ float    gath[NWARP][GCAP];
    __shared__ unsigned s_gn[NWARP];
    __shared__ unsigned s_out[NWARP][3];
    __shared__ float    s_bsum[NWARP];
    __shared__ float    s_red[NWARP];
    __shared__ unsigned s_flag;

    const int tid  = threadIdx.x;
    const int lane = tid & 31;
    const int wid  = tid >> 5;
    const int row  = blockIdx.x * NWARP + wid;     // one row per warp

    const float* __restrict__ rowp = in + (size_t)row * NCOLS;
    const int tgt = tg[row];

    float*    mycand = cand[wid];
    unsigned* myhist = hist[wid];

    // zero my warp's hist + flags (warp-private; no cross-warp sync needed)
    #pragma unroll
    for (int j = 0; j < NB / 32; ++j) myhist[lane + j * 32] = 0;
    if (lane == 0) { s_gn[wid] = 0; s_out[wid][0] = SENT; }

    // ---- sweep: each lane streams 128 float4, compacts to private slots ----
    const float4* __restrict__ p = (const float4*)rowp;
    unsigned mycnt = 0;
    #pragma unroll 8
    for (int it = 0; it < NCOLS / 4 / 32; ++it) {  // 128 iterations
        float4 f = __ldcs(&p[it * 32 + lane]);
        if (f.x > THR0) { if (mycnt < SLOTS) mycand[mycnt * 32 + lane] = f.x; ++mycnt; }
        if (f.y > THR0) { if (mycnt < SLOTS) mycand[mycnt * 32 + lane] = f.y; ++mycnt; }
        if (f.z > THR0) { if (mycnt < SLOTS) mycand[mycnt * 32 + lane] = f.z; ++mycnt; }
        if (f.w > THR0) { if (mycnt < SLOTS) mycand[mycnt * 32 + lane] = f.w; ++mycnt; }
    }
    const unsigned nc  = __reduce_add_sync(FULLM, mycnt);
    const unsigned ovf = __ballot_sync(FULLM, mycnt > SLOTS);
    const unsigned n_i = mycnt < SLOTS ? mycnt : SLOTS;

    const float    pos    = rowp[tgt];             // broadcast load
    const unsigned pos_in = (pos > THR0) ? 1u : 0u;
    bool gmode = (nc < KHARD + pos_in) || ovf;

    float sum = 0.0f;
    bool use_key = false;
    unsigned tkey = 0, rmul = 0;
    int bbin = NB;

    if (!gmode) {
        // warp-private histogram from own slots
        for (unsigned i = 0; i < n_i; ++i)
            atomicAdd(&myhist[binof(mycand[i * 32 + lane])], 1u);
        if (lane == 0 && pos_in) atomicSub(&myhist[binof(pos)], 1u);
        __syncwarp();

        wselect256(myhist, KHARD, s_out[wid]);     // total >= KHARD here: always found
        __syncwarp();
        bbin = (int)s_out[wid][0];
        const unsigned rp = KHARD - s_out[wid][1];

        // fused pass over OWN candidates: strict sum + boundary gather
        for (unsigned i = 0; i < n_i; ++i) {
            float x = mycand[i * 32 + lane];
            int b = binof(x);
            if (b > bbin) sum += softplus(x);
            else if (b == bbin) {
                unsigned g = atomicAdd(&s_gn[wid], 1u);
                if (g < GCAP) gath[wid][g] = x;
            }
        }
        __syncwarp();

        if (s_gn[wid] > GCAP) { gmode = true; sum = 0.0f; }
        else if (lane == 0) {
            int n = (int)s_gn[wid];
            float* gg = gath[wid];
            if (pos_in && binof(pos) == bbin) {    // drop one positive instance
                for (int j = 0; j < n; ++j)
                    if (gg[j] == pos) { gg[j] = gg[n - 1]; --n; break; }
            }
            float bs = 0.0f;                       // top-rp of the boundary bin
            for (int a = 0; a < (int)rp; ++a) {
                int mi = a; float mv = gg[a];
                for (int b2 = a + 1; b2 < n; ++b2)
                    if (gg[b2] > mv) { mv = gg[b2]; mi = b2; }
                gg[mi] = gg[a]; gg[a] = mv;
                bs += softplus(mv);
            }
            s_bsum[wid] = bs;
        }
        __syncwarp();
    }

    if (gmode) {
        // exact warp-level 4x8-bit fkey radix select from gmem (L2-resident)
        use_key = true;
        unsigned prefix = 0, r = KHARD;
        for (int lev = 0; lev < 4; ++lev) {
            const int shift = 24 - 8 * lev;
            #pragma unroll
            for (int j = 0; j < NB / 32; ++j) myhist[lane + j * 32] = 0;
            if (lane == 0) s_out[wid][0] = 0;      // full row: always found
            __syncwarp();
            for (int j = lane; j < NCOLS; j += 32) {
                if (j == tgt) continue;
                unsigned u = fkey(rowp[j]);
                bool match = (lev == 0) || (((u ^ prefix) >> (shift + 8)) == 0u);
                if (match) atomicAdd(&myhist[(u >> shift) & 255u], 1u);
            }
            __syncwarp();
            wselect256(myhist, r, s_out[wid]);
            __syncwarp();
            prefix |= s_out[wid][0] << shift;
            r -= s_out[wid][1];
            __syncwarp();
        }
        tkey = prefix; rmul = r;
        for (int j = lane; j < NCOLS; j += 32) {
            if (j == tgt) continue;
            float x = rowp[j];
            if (fkey(x) > tkey) sum += softplus(x);
        }
    }

    // ---- warp reduce strict sum, lane 0 writes the row partial ----
    #pragma unroll
    for (int o = 16; o; o >>= 1) sum += __shfl_down_sync(FULLM, sum, o);
    if (lane == 0) {
        float tot = sum;
        if (!use_key) {
            if (pos_in && binof(pos) > bbin) tot -= softplus(pos);
            tot += s_bsum[wid];
        } else {
            tot += (float)rmul * softplus(unfkey(tkey));
        }
        g_partials[row] = DELTA_W * softplus(-pos) + tot / (float)KHARD;
    }

    // ---- CTA handshake; last CTA reduces all rows ----
    __syncthreads();
    if (tid == 0) {
        __threadfence();
        unsigned old = atomicAdd(&g_done, 1u);
        s_flag = (old == GRIDSZ - 1) ? 1u : 0u;
    }
    __syncthreads();

    if (s_flag) {
        __threadfence();
        float s = 0.0f;
        for (int i = tid; i < MROWS; i += NT) s += __ldcg(&g_partials[i]);
        #pragma unroll
        for (int o = 16; o; o >>= 1) s += __shfl_down_sync(FULLM, s, o);
        if (lane == 0) s_red[wid] = s;
        __syncthreads();
        if (tid == 0) {
            float tot = 0.0f;
            #pragma unroll
            for (int w = 0; w < NWARP; ++w) tot += s_red[w];
            out[0] = tot / (float)MROWS;
            g_done = 0;                            // reset for next graph replay
        }
    }
}

extern "C" void kernel_launch(void* const* d_in, const int* in_sizes, int n_in,
                              void* d_out, int out_size)
{
    const float* in  = (const float*)d_in[0];
    const int*   tg  = (const int*)d_in[1];
    float*       out = (float*)d_out;
    mmcl_kernel<<<GRIDSZ, NT>>>(in, tg, out);
}

// round 16
// speedup vs baseline: 1.0611x; 1.0611x over previous
#include <cuda_runtime.h>
#include <math.h>
#include <float.h>

#define MROWS   4096
#define NCOLS   16384
#define KHARD   163          // int(0.01 * (16384-1))
#define DELTA_W 5.0f
#define THR0    2.2f
#define NT      128
#define NWARP   (NT / 32)
#define SLOTS   16           // per-thread private candidate slots
#define NB      256          // linear value bins over [THR0, THR0+4)
#define GCAP    64
#define GRIDSZ  2048         // 2 rows per CTA, single wave
#define SENT    0xFFFFFFFFu
#define FULLM   0xFFFFFFFFu

__device__ float    g_partials[MROWS];
__device__ unsigned g_done = 0;

__device__ __forceinline__ unsigned fkey(float x) {
    unsigned b = __float_as_uint(x);
    return (b & 0x80000000u) ? ~b : (b | 0x80000000u);
}
__device__ __forceinline__ float unfkey(unsigned k) {
    return (k & 0x80000000u) ? __uint_as_float(k ^ 0x80000000u) : __uint_as_float(~k);
}
__device__ __forceinline__ float softplus(float x) {
    // fast + stable: max(x,0) + log(1 + exp(-|x|)); MUFU-only transcendentals
    return fmaxf(x, 0.0f) + __logf(1.0f + __expf(-fabsf(x)));
}
__device__ __forceinline__ int binof(float x) {          // x > THR0
    int b = (int)((x - THR0) * 64.0f);                   // NB/4 per unit
    return b > NB - 1 ? NB - 1 : b;
}
__device__ __forceinline__ void prefetch_l2(const float* p) {
    asm volatile("prefetch.global.L2 [%0];" :: "l"(p));
}

// Boundary-bin search for the r-th largest over hist[0..B).
// Writes s_out = {bin, strictly-above count, bin count} ONLY if the histogram
// total reaches r; otherwise s_out[0] keeps its prior (sentinel) value.
// 2 barriers.
__device__ __forceinline__ void select_bin(const unsigned* __restrict__ hist, int B,
                                           unsigned r, unsigned* s_warpS,
                                           unsigned* s_out)
{
    const int tid = threadIdx.x, lane = tid & 31, wid = tid >> 5;
    const int c = (B + NT - 1) / NT;
    unsigned total = 0;
    const int base = tid * c;
    for (int j = 0; j < c; ++j)
        if (base + j < B) total += hist[base + j];
    unsigned incl = total;
    #pragma unroll
    for (int off = 1; off < 32; off <<= 1) {
        unsigned v = __shfl_down_sync(FULLM, incl, off);
        if (lane + off < 32) incl += v;
    }
    if (lane == 0) s_warpS[wid] = incl;
    __syncthreads();
    unsigned hi = 0;
    #pragma unroll
    for (int w = 0; w < NWARP; ++w) if (w > wid) hi += s_warpS[w];
    unsigned S = incl + hi;
    unsigned above_chunk = S - total;
    if (above_chunk < r && S >= r) {         // boundary in my chunk (at most one thread)
        unsigned run = above_chunk;
        for (int j = c - 1; j >= 0; --j) {
            if (base + j >= B) continue;
            unsigned cnt = hist[base + j];
            if (run + cnt >= r) { s_out[0] = base + j; s_out[1] = run; s_out[2] = cnt; break; }
            run += cnt;
        }
    }
    __syncthreads();
}

extern "C" __global__ void __launch_bounds__(NT, 16)
mmcl_kernel(const float* __restrict__ in, const int* __restrict__ tg,
            float* __restrict__ out)
{
    __shared__ float    cand[SLOTS * NT];       // 8 KB, interleaved per-thread segments
    __shared__ unsigned hist[NB];               // 1 KB
    __shared__ unsigned s_gn, s_flag, s_ovf;
    __shared__ unsigned s_warpS[NWARP];
    __shared__ unsigned s_out[3];
    __shared__ float    s_red[NWARP];
    __shared__ float    s_gath[GCAP];
    __shared__ float    s_pos, s_bsum;

    const int tid  = threadIdx.x;
    const int lane = tid & 31;
    const int wid  = tid >> 5;

    #pragma unroll 1
    for (int rep = 0; rep < 2; ++rep) {
        const int row = blockIdx.x + rep * GRIDSZ;
        const float* __restrict__ rowp = in + (size_t)row * NCOLS;
        const int tgt = tg[row];

        __syncthreads();                         // protect smem reuse across rows
        for (int i = tid; i < NB / 4; i += NT)
            ((uint4*)hist)[i] = make_uint4(0, 0, 0, 0);
        if (tid == 0) { s_gn = 0; s_ovf = 0; s_out[0] = SENT; s_pos = rowp[tgt]; }

        // ---- minimal sweep: private-slot compaction only ----
        const float4* __restrict__ p = (const float4*)rowp;
        const float*  nxt = in + (size_t)(row + GRIDSZ) * NCOLS;   // row B base
        unsigned mycnt = 0;
        #pragma unroll 8
        for (int it = 0; it < 16; ++it) {        // first half of the row
            float4 f = __ldcs(&p[it * NT + tid]);
            if (f.x > THR0) { if (mycnt < SLOTS) cand[mycnt * NT + tid] = f.x; ++mycnt; }
            if (f.y > THR0) { if (mycnt < SLOTS) cand[mycnt * NT + tid] = f.y; ++mycnt; }
            if (f.z > THR0) { if (mycnt < SLOTS) cand[mycnt * NT + tid] = f.z; ++mycnt; }
            if (f.w > THR0) { if (mycnt < SLOTS) cand[mycnt * NT + tid] = f.w; ++mycnt; }
        }
        if (rep == 0) {                          // early half-prefetch of row B
            prefetch_l2(nxt + (0 * NT + tid) * 32);
            prefetch_l2(nxt + (1 * NT + tid) * 32);
        }
        #pragma unroll 8
        for (int it = 16; it < 32; ++it) {       // second half of the row
            float4 f = __ldcs(&p[it * NT + tid]);
            if (f.x > THR0) { if (mycnt < SLOTS) cand[mycnt * NT + tid] = f.x; ++mycnt; }
            if (f.y > THR0) { if (mycnt < SLOTS) cand[mycnt * NT + tid] = f.y; ++mycnt; }
            if (f.z > THR0) { if (mycnt < SLOTS) cand[mycnt * NT + tid] = f.z; ++mycnt; }
            if (f.w > THR0) { if (mycnt < SLOTS) cand[mycnt * NT + tid] = f.w; ++mycnt; }
        }
        if (rep == 0) {                          // remaining half-prefetch of row B
            prefetch_l2(nxt + (2 * NT + tid) * 32);
            prefetch_l2(nxt + (3 * NT + tid) * 32);
        }
        if (mycnt > SLOTS) s_ovf = 1u;           // benign race: only ever set to 1

        const unsigned n_i = mycnt < SLOTS ? mycnt : SLOTS;
        __syncthreads();                         // hist zero + s_pos/s_ovf/s_out ordering

        // ---- histogram from own slots; positive removed algebraically ----
        const float pos = s_pos;
        const unsigned pos_in = (pos > THR0) ? 1u : 0u;
        for (unsigned i = 0; i < n_i; ++i)
            atomicAdd(&hist[binof(cand[i * NT + tid])], 1u);
        if (tid == 0 && pos_in) atomicSub(&hist[binof(pos)], 1u);
        __syncthreads();

        // underflow (hist total < KHARD) leaves s_out[0] == SENT
        select_bin(hist, NB, KHARD, s_warpS, s_out);

        bool gmode = (s_out[0] == SENT) || (s_ovf != 0u);
        float sum = 0.0f;
        bool use_key = false;
        unsigned tkey = 0, rmul = 0;
        int bbin = NB;

        if (!gmode) {
            bbin = (int)s_out[0];
            const unsigned rp = KHARD - s_out[1];

            // fused pass over OWN candidates: strict sum + boundary gather
            for (unsigned i = 0; i < n_i; ++i) {
                float x = cand[i * NT + tid];
                int b = binof(x);
                if (b > bbin) sum += softplus(x);
                else if (b == bbin) {
                    unsigned g = atomicAdd(&s_gn, 1u);
                    if (g < GCAP) s_gath[g] = x;
                }
            }
            __syncthreads();

            if (s_gn > GCAP) { gmode = true; sum = 0.0f; }
            else if (tid == 0) {
                int n = (int)s_gn;
                if (pos_in && binof(pos) == bbin) {       // drop one positive instance
                    for (int j = 0; j < n; ++j)
                        if (s_gath[j] == pos) { s_gath[j] = s_gath[n - 1]; --n; break; }
                }
                float bs = 0.0f;                          // top-rp of the boundary bin
                for (int a = 0; a < (int)rp; ++a) {
                    int mi = a; float mv = s_gath[a];
                    for (int b2 = a + 1; b2 < n; ++b2)
                        if (s_gath[b2] > mv) { mv = s_gath[b2]; mi = b2; }
                    s_gath[mi] = s_gath[a]; s_gath[a] = mv;
                    bs += softplus(mv);
                }
                s_bsum = bs;
            }
        }

        if (gmode) {
            // exact 4x8-bit fkey radix select from gmem; never fires for N(0,1)
            use_key = true;
            unsigned prefix = 0, r = KHARD;
            for (int lev = 0; lev < 4; ++lev) {
                const int shift = 24 - 8 * lev;
                for (int i = tid; i < 256; i += NT) hist[i] = 0;
                if (tid == 0) s_out[0] = 0;               // full subset: always found
                __syncthreads();
                for (int j = tid; j < NCOLS; j += NT) {
                    if (j == tgt) continue;
                    unsigned u = fkey(rowp[j]);
                    bool match = (lev == 0) || (((u ^ prefix) >> (shift + 8)) == 0u);
                    if (match) atomicAdd(&hist[(u >> shift) & 255u], 1u);
                }
                __syncthreads();
                select_bin(hist, 256, r, s_warpS, s_out);
                prefix |= s_out[0] << shift;
                r -= s_out[1];
                __syncthreads();
            }
            tkey = prefix; rmul = r;
            for (int j = tid; j < NCOLS; j += NT) {
                if (j == tgt) continue;
                float x = rowp[j];
                if (fkey(x) > tkey) sum += softplus(x);
            }
        }

        // ---- block reduce strict sum, write row partial ----
        #pragma unroll
        for (int o = 16; o; o >>= 1) sum += __shfl_down_sync(FULLM, sum, o);
        if (lane == 0) s_red[wid] = sum;
        __syncthreads();

        if (tid == 0) {
            float tot = 0.0f;
            #pragma unroll
            for (int w = 0; w < NWARP; ++w) tot += s_red[w];
            if (!use_key) {
                if (pos_in && binof(pos) > bbin) tot -= softplus(pos);
                tot += s_bsum;
            } else {
                tot += (float)rmul * softplus(unfkey(tkey));
            }
            g_partials[row] = DELTA_W * softplus(-pos) + tot / (float)KHARD;
        }
    }

    // ---- once per CTA: completion handshake; last CTA reduces all rows ----
    __syncthreads();
    if (tid == 0) {
        __threadfence();
        unsigned old = atomicAdd(&g_done, 1u);
        s_flag = (old == GRIDSZ - 1) ? 1u : 0u;
    }
    __syncthreads();

    if (s_flag) {
        __threadfence();
        float s = 0.0f;
        for (int i = tid; i < MROWS; i += NT) s += __ldcg(&g_partials[i]);
        #pragma unroll
        for (int o = 16; o; o >>= 1) s += __shfl_down_sync(FULLM, s, o);
        if (lane == 0) s_red[wid] = s;
        __syncthreads();
        if (tid == 0) {
            float tot = 0.0f;
            #pragma unroll
            for (int w = 0; w < NWARP; ++w) tot += s_red[w];
            out[0] = tot / (float)MROWS;
            g_done = 0;                               // reset for next graph replay
        }
    }
}

extern "C" void kernel_launch(void* const* d_in, const int* in_sizes, int n_in,
                              void* d_out, int out_size)
{
    const float* in  = (const float*)d_in[0];
    const int*   tg  = (const int*)d_in[1];
    float*       out = (float*)d_out;
    mmcl_kernel<<<GRIDSZ, NT>>>(in, tg, out);
}

// round 17
// speedup vs baseline: 1.1695x; 1.1022x over previous
#include <cuda_runtime.h>
#include <math.h>
#include <float.h>

#define MROWS   4096
#define NCOLS   16384
#define KHARD   163          // int(0.01 * (16384-1))
#define DELTA_W 5.0f
#define THR0    2.2f
#define NT      128
#define NWARP   (NT / 32)
#define SLOTS   16           // per-thread private candidate slots
#define NB      256          // linear value bins over [THR0, THR0+4)
#define GCAP    64
#define GRIDSZ  2048         // 2 rows per CTA, single wave at 14 CTAs/SM
#define FULLM   0xFFFFFFFFu

__device__ float    g_partials[MROWS];
__device__ unsigned g_done = 0;

__device__ __forceinline__ unsigned fkey(float x) {
    unsigned b = __float_as_uint(x);
    return (b & 0x80000000u) ? ~b : (b | 0x80000000u);
}
__device__ __forceinline__ float unfkey(unsigned k) {
    return (k & 0x80000000u) ? __uint_as_float(k ^ 0x80000000u) : __uint_as_float(~k);
}
__device__ __forceinline__ float softplus(float x) {
    // fast + stable: max(x,0) + log(1 + exp(-|x|)); MUFU-only transcendentals
    return fmaxf(x, 0.0f) + __logf(1.0f + __expf(-fabsf(x)));
}
__device__ __forceinline__ int binof(float x) {          // x > THR0
    int b = (int)((x - THR0) * 64.0f);                   // NB/4 per unit
    return b > NB - 1 ? NB - 1 : b;
}
__device__ __forceinline__ void prefetch_l2(const float* p) {
    asm volatile("prefetch.global.L2 [%0];" :: "l"(p));
}

// Boundary-bin search for the r-th largest over hist[0..B).
// s_out = {bin, count strictly above bin, bin count}. 2 barriers.
__device__ __forceinline__ void select_bin(const unsigned* __restrict__ hist, int B,
                                           unsigned r, unsigned* s_warpS,
                                           unsigned* s_out)
{
    const int tid = threadIdx.x, lane = tid & 31, wid = tid >> 5;
    const int c = (B + NT - 1) / NT;
    unsigned total = 0;
    const int base = tid * c;
    for (int j = 0; j < c; ++j)
        if (base + j < B) total += hist[base + j];
    unsigned incl = total;
    #pragma unroll
    for (int off = 1; off < 32; off <<= 1) {
        unsigned v = __shfl_down_sync(FULLM, incl, off);
        if (lane + off < 32) incl += v;
    }
    if (lane == 0) s_warpS[wid] = incl;
    __syncthreads();
    unsigned hi = 0;
    #pragma unroll
    for (int w = 0; w < NWARP; ++w) if (w > wid) hi += s_warpS[w];
    unsigned S = incl + hi;
    unsigned above_chunk = S - total;
    if (above_chunk < r && S >= r) {
        unsigned run = above_chunk;
        for (int j = c - 1; j >= 0; --j) {
            if (base + j >= B) continue;
            unsigned cnt = hist[base + j];
            if (run + cnt >= r) { s_out[0] = base + j; s_out[1] = run; s_out[2] = cnt; break; }
            run += cnt;
        }
    }
    __syncthreads();
}

extern "C" __global__ void __launch_bounds__(NT, 14)
mmcl_kernel(const float* __restrict__ in, const int* __restrict__ tg,
            float* __restrict__ out)
{
    __shared__ float    cand[SLOTS * NT];       // 8 KB, interleaved per-thread segments
    __shared__ unsigned hist[NB];               // 1 KB
    __shared__ unsigned s_gn, s_flag;
    __shared__ unsigned s_warpS[NWARP];
    __shared__ unsigned s_out[3];
    __shared__ float    s_red[NWARP];
    __shared__ float    s_gath[GCAP];
    __shared__ float    s_pos, s_bsum;

    const int tid  = threadIdx.x;
    const int lane = tid & 31;
    const int wid  = tid >> 5;

    #pragma unroll 1
    for (int rep = 0; rep < 2; ++rep) {
        const int row = blockIdx.x + rep * GRIDSZ;
        const float* __restrict__ rowp = in + (size_t)row * NCOLS;
        const int tgt = tg[row];

        __syncthreads();                         // protect smem reuse across rows
        for (int i = tid; i < NB / 4; i += NT)
            ((uint4*)hist)[i] = make_uint4(0, 0, 0, 0);
        if (tid == 0) { s_gn = 0; s_pos = rowp[tgt]; }

        // ---- minimal sweep: private-slot compaction only ----
        const float4* __restrict__ p = (const float4*)rowp;
        unsigned mycnt = 0;
        #pragma unroll 8
        for (int it = 0; it < NCOLS / 4 / NT; ++it) {    // 32 iterations
            float4 f = __ldcs(&p[it * NT + tid]);
            if (f.x > THR0) { if (mycnt < SLOTS) cand[mycnt * NT + tid] = f.x; ++mycnt; }
            if (f.y > THR0) { if (mycnt < SLOTS) cand[mycnt * NT + tid] = f.y; ++mycnt; }
            if (f.z > THR0) { if (mycnt < SLOTS) cand[mycnt * NT + tid] = f.z; ++mycnt; }
            if (f.w > THR0) { if (mycnt < SLOTS) cand[mycnt * NT + tid] = f.w; ++mycnt; }
        }

        // ---- fire-and-forget L2 prefetch of the NEXT row (overlaps select below) ----
        if (rep == 0) {
            const float* nxt = in + (size_t)(row + GRIDSZ) * NCOLS;
            #pragma unroll
            for (int j = 0; j < 4; ++j)                   // 4 x 128 thr = 512 lines x 128B
                prefetch_l2(nxt + (j * NT + tid) * 32);
        }

        const unsigned wsum = __reduce_add_sync(FULLM, mycnt);
        const unsigned wovf = __ballot_sync(FULLM, mycnt > SLOTS);
        if (lane == 0) s_warpS[wid] = (wsum << 1) | (wovf ? 1u : 0u);
        __syncthreads();
        unsigned nc = 0, ovf = 0;
        #pragma unroll
        for (int w = 0; w < NWARP; ++w) { nc += s_warpS[w] >> 1; ovf |= s_warpS[w] & 1u; }

        const float    pos = s_pos;
        const unsigned pos_in = (pos > THR0) ? 1u : 0u;
        bool gmode = (nc < KHARD + pos_in) || ovf;

        float sum = 0.0f;
        bool use_key = false;
        unsigned tkey = 0, rmul = 0;
        int bbin = NB;

        if (!gmode) {
            // histogram from own slots (few elements each)
            for (unsigned i = 0; i < mycnt; ++i)
                atomicAdd(&hist[binof(cand[i * NT + tid])], 1u);
            if (tid == 0 && pos_in) atomicSub(&hist[binof(pos)], 1u);
            __syncthreads();

            select_bin(hist, NB, KHARD, s_warpS, s_out);
            bbin = (int)s_out[0];
            const unsigned rp = KHARD - s_out[1];

            // fused pass over OWN candidates: strict sum + boundary gather
            for (unsigned i = 0; i < mycnt; ++i) {
                float x = cand[i * NT + tid];
                int b = binof(x);
                if (b > bbin) sum += softplus(x);
                else if (b == bbin) {
                    unsigned g = atomicAdd(&s_gn, 1u);
                    if (g < GCAP) s_gath[g] = x;
                }
            }
            __syncthreads();

            const int n = (int)s_gn;
            if ((unsigned)n > GCAP) { gmode = true; sum = 0.0f; }
            else if (n <= 32) {
                // warp-parallel boundary resolve (warp 0): rank-select the exact
                // top-rp multiset (index tie-break), one positive instance excluded
                if (tid < 32) {
                    float x = (lane < n) ? s_gath[lane] : -FLT_MAX;
                    int jp = -1;                          // one positive instance to drop
                    if (pos_in && binof(pos) == bbin) {
                        unsigned pm = __ballot_sync(FULLM, (lane < n) && (x == pos));
                        if (pm) jp = __ffs(pm) - 1;
                    }
                    int rank = 0;
                    for (int b2 = 0; b2 < n; ++b2) {
                        float xb = __shfl_sync(FULLM, x, b2);
                        if (b2 != jp && (xb > x || (xb == x && b2 < lane))) ++rank;
                    }
                    bool inc = (lane < n) && (lane != jp) && (rank < (int)rp);
                    float v = inc ? softplus(x) : 0.0f;
                    #pragma unroll
                    for (int o = 16; o; o >>= 1) v += __shfl_down_sync(FULLM, v, o);
                    if (lane == 0) s_bsum = v;
                }
            } else if (tid == 0) {
                // rare wide-bin case: serial resolve (exact, proven path)
                int nn = n;
                if (pos_in && binof(pos) == bbin) {
                    for (int j = 0; j < nn; ++j)
                        if (s_gath[j] == pos) { s_gath[j] = s_gath[nn - 1]; --nn; break; }
                }
                float bs = 0.0f;
                for (int a = 0; a < (int)rp; ++a) {
                    int mi = a; float mv = s_gath[a];
                    for (int b2 = a + 1; b2 < nn; ++b2)
                        if (s_gath[b2] > mv) { mv = s_gath[b2]; mi = b2; }
                    s_gath[mi] = s_gath[a]; s_gath[a] = mv;
                    bs += softplus(mv);
                }
                s_bsum = bs;
            }
        }

        if (gmode) {
            // exact 4x8-bit fkey radix select from gmem; never fires for N(0,1)
            use_key = true;
            unsigned prefix = 0, r = KHARD;
            for (int lev = 0; lev < 4; ++lev) {
                const int shift = 24 - 8 * lev;
                for (int i = tid; i < 256; i += NT) hist[i] = 0;
                __syncthreads();
                for (int j = tid; j < NCOLS; j += NT) {
                    if (j == tgt) continue;
                    unsigned u = fkey(rowp[j]);
                    bool match = (lev == 0) || (((u ^ prefix) >> (shift + 8)) == 0u);
                    if (match) atomicAdd(&hist[(u >> shift) & 255u], 1u);
                }
                __syncthreads();
                select_bin(hist, 256, r, s_warpS, s_out);
                prefix |= s_out[0] << shift;
                r -= s_out[1];
                __syncthreads();
            }
            tkey = prefix; rmul = r;
            for (int j = tid; j < NCOLS; j += NT) {
                if (j == tgt) continue;
                float x = rowp[j];
                if (fkey(x) > tkey) sum += softplus(x);
            }
        }

        // ---- block reduce strict sum, write row partial ----
        #pragma unroll
        for (int o = 16; o; o >>= 1) sum += __shfl_down_sync(FULLM, sum, o);
        if (lane == 0) s_red[wid] = sum;
        __syncthreads();

        if (tid == 0) {
            float tot = 0.0f;
            #pragma unroll
            for (int w = 0; w < NWARP; ++w) tot += s_red[w];
            if (!use_key) {
                if (pos_in && binof(pos) > bbin) tot -= softplus(pos);
                tot += s_bsum;
            } else {
                tot += (float)rmul * softplus(unfkey(tkey));
            }
            g_partials[row] = DELTA_W * softplus(-pos) + tot / (float)KHARD;
        }
    }

    // ---- once per CTA: completion handshake; last CTA reduces all rows ----
    __syncthreads();
    if (tid == 0) {
        __threadfence();
        unsigned old = atomicAdd(&g_done, 1u);
        s_flag = (old == GRIDSZ - 1) ? 1u : 0u;
    }
    __syncthreads();

    if (s_flag) {
        __threadfence();
        float s = 0.0f;
        for (int i = tid; i < MROWS; i += NT) s += __ldcg(&g_partials[i]);
        #pragma unroll
        for (int o = 16; o; o >>= 1) s += __shfl_down_sync(FULLM, s, o);
        if (lane == 0) s_red[wid] = s;
        __syncthreads();
        if (tid == 0) {
            float tot = 0.0f;
            #pragma unroll
            for (int w = 0; w < NWARP; ++w) tot += s_red[w];
            out[0] = tot / (float)MROWS;
            g_done = 0;                               // reset for next graph replay
        }
    }
}

extern "C" void kernel_launch(void* const* d_in, const int* in_sizes, int n_in,
                              void* d_out, int out_size)
{
    const float* in  = (const float*)d_in[0];
    const int*   tg  = (const int*)d_in[1];
    float*       out = (float*)d_out;
    mmcl_kernel<<<GRIDSZ, NT>>>(in, tg, out);
}